// round 13
// baseline (speedup 1.0000x reference)
#include <cuda_runtime.h>
#include <cuda_fp16.h>
#include <cstdint>

#define WINDOW 512
#define S_LEN  4096
#define BH     16
#define TQ     128
#define TK     64
#define DD     64
#define NTH    256

// smem: Q fp16 (16KB) + 2-stage K/V fp16 ring (2 x 16KB) = 48KB/CTA
#define SM_Q  0
#define SM_STG(s) (16384 + (s) * 16384)
#define OFF_K 0
#define OFF_V 8192
#define SM_TOTAL 49152

#define SWZ(x) ((x) ^ (((x) >> 3) & 0x70))

// fp16 K/V scratch: 16 * 4096 * 64 halves = 8MB each
#define KV_CHUNKS (BH * S_LEN * DD / 8)
__device__ uint4 g_kh[KV_CHUNKS];
__device__ uint4 g_vh[KV_CHUNKS];

static __device__ __forceinline__ uint32_t s2u(const void* p) {
    uint32_t a;
    asm("{ .reg .u64 t; cvta.to.shared.u64 t, %1; cvt.u32.u64 %0, t; }" : "=r"(a) : "l"(p));
    return a;
}
static __device__ __forceinline__ float ex2f_(float x) {
    float y; asm("ex2.approx.f32 %0,%1;" : "=f"(y) : "f"(x)); return y;
}
static __device__ __forceinline__ uint32_t pack2h(float a, float b) {
    uint32_t r;
    asm("cvt.rn.f16x2.f32 %0, %1, %2;" : "=r"(r) : "f"(b), "f"(a));
    return r;
}

static __device__ __forceinline__ void ldsm4(uint32_t r[4], uint32_t addr) {
    asm volatile("ldmatrix.sync.aligned.m8n8.x4.shared.b16 {%0,%1,%2,%3}, [%4];"
                 : "=r"(r[0]), "=r"(r[1]), "=r"(r[2]), "=r"(r[3]) : "r"(addr));
}
static __device__ __forceinline__ void ldsm4t(uint32_t r[4], uint32_t addr) {
    asm volatile("ldmatrix.sync.aligned.m8n8.x4.trans.shared.b16 {%0,%1,%2,%3}, [%4];"
                 : "=r"(r[0]), "=r"(r[1]), "=r"(r[2]), "=r"(r[3]) : "r"(addr));
}
static __device__ __forceinline__ void mma16816(float c[4], const uint32_t a[4],
                                                uint32_t b0, uint32_t b1) {
    asm volatile(
        "mma.sync.aligned.m16n8k16.row.col.f32.f16.f16.f32 "
        "{%0,%1,%2,%3}, {%4,%5,%6,%7}, {%8,%9}, {%0,%1,%2,%3};"
        : "+f"(c[0]), "+f"(c[1]), "+f"(c[2]), "+f"(c[3])
        : "r"(a[0]), "r"(a[1]), "r"(a[2]), "r"(a[3]), "r"(b0), "r"(b1));
}
static __device__ __forceinline__ void cpasync16(uint32_t sdst, const void* gsrc) {
    asm volatile("cp.async.cg.shared.global [%0], [%1], 16;"
                 :: "r"(sdst), "l"(gsrc) : "memory");
}

// 16 floats -> scaled fp16 tile (two 16B stores)
static __device__ __forceinline__ void store16h(const float4* g, char* s, int rel, float scale) {
    float4 f[4];
    #pragma unroll
    for (int i = 0; i < 4; i++) f[i] = g[i];
    uint32_t w[8];
    #pragma unroll
    for (int i = 0; i < 4; i++) {
        w[2 * i]     = pack2h(f[i].x * scale, f[i].y * scale);
        w[2 * i + 1] = pack2h(f[i].z * scale, f[i].w * scale);
    }
    *(uint4*)(s + SWZ(rel))      = make_uint4(w[0], w[1], w[2], w[3]);
    *(uint4*)(s + SWZ(rel + 16)) = make_uint4(w[4], w[5], w[6], w[7]);
}

// ---- prepass: K,V fp32 -> fp16 scratch; 2 chunks per tensor per thread (MLP 8) ----
__global__ void __launch_bounds__(256)
cvt_kv_kernel(const float* __restrict__ Kp, const float* __restrict__ Vp) {
    const int i = (blockIdx.x * 256 + threadIdx.x) * 2;   // exact: grid*256*2 == KV_CHUNKS
    const float4* ks = (const float4*)(Kp + (size_t)i * 8);
    const float4* vs = (const float4*)(Vp + (size_t)i * 8);
    float4 a = ks[0], b = ks[1], c = ks[2], d = ks[3];
    float4 e = vs[0], f = vs[1], g = vs[2], h = vs[3];
    g_kh[i]     = make_uint4(pack2h(a.x, a.y), pack2h(a.z, a.w),
                             pack2h(b.x, b.y), pack2h(b.z, b.w));
    g_kh[i + 1] = make_uint4(pack2h(c.x, c.y), pack2h(c.z, c.w),
                             pack2h(d.x, d.y), pack2h(d.z, d.w));
    g_vh[i]     = make_uint4(pack2h(e.x, e.y), pack2h(e.z, e.w),
                             pack2h(f.x, f.y), pack2h(f.z, f.w));
    g_vh[i + 1] = make_uint4(pack2h(g.x, g.y), pack2h(g.z, g.w),
                             pack2h(h.x, h.y), pack2h(h.z, h.w));
}

extern __shared__ __align__(1024) char smem[];

__global__ void __launch_bounds__(NTH, 2)
swa_mma_kernel(const float* __restrict__ Qp, float* __restrict__ Op) {
    const int tid  = threadIdx.x;
    const int lane = tid & 31;
    const int warp = tid >> 5;
    const int bh   = blockIdx.y;
    const int q0   = blockIdx.x * TQ;
    const size_t base = (size_t)bh * S_LEN * DD;
    const uint32_t sb = s2u(smem);

    // staging coords for cp.async
    const int srow = tid >> 2;
    const int sc0  = (tid & 3) * 32;
    const char* gk = (const char*)g_kh + (size_t)bh * S_LEN * 128;
    const char* gv = (const char*)g_vh + (size_t)bh * S_LEN * 128;

    const int kt0 = (q0 >= WINDOW - 1) ? ((q0 - WINDOW + 1) >> 6) : 0;
    const int kt1 = (q0 + TQ - 1) >> 6;

    // ---- prologue: async-load tile kt0 into stage 0 ----
    {
        const char* ks = gk + (size_t)(kt0 * TK + srow) * 128 + sc0;
        const char* vs = gv + (size_t)(kt0 * TK + srow) * 128 + sc0;
        const uint32_t d = sb + SM_STG(0);
        cpasync16(d + OFF_K + SWZ(srow * 128 + sc0),      ks);
        cpasync16(d + OFF_K + SWZ(srow * 128 + sc0 + 16), ks + 16);
        cpasync16(d + OFF_V + SWZ(srow * 128 + sc0),      vs);
        cpasync16(d + OFF_V + SWZ(srow * 128 + sc0 + 16), vs + 16);
        asm volatile("cp.async.commit_group;" ::: "memory");
    }

    // ---- stage Q (128x64) as fp16, pre-scaled to log2 domain ----
    {
        const float qs = 0.125f * 1.44269504088896340736f;
        const int trow = tid >> 2, q4 = tid & 3;
        #pragma unroll
        for (int half = 0; half < 2; half++) {
            const int row = trow + half * 64;
            const float4* g = (const float4*)(Qp + base + (size_t)(q0 + row) * DD + q4 * 16);
            store16h(g, smem + SM_Q, row * 128 + q4 * 32, qs);
        }
    }
    __syncthreads();

    // per-lane fragment address components
    const int g_   = lane >> 2;
    const int tig  = lane & 3;
    const int rowA = (warp << 4) + (lane & 15);
    const int cA16 = (lane >> 4) * 16;
    const int rkK  = (lane & 7) + ((lane >> 4) & 1) * 8;
    const int cK16 = ((lane >> 3) & 1) * 16;
    const int rkV  = (lane & 7) + ((lane >> 3) & 1) * 8;
    const int cV16 = ((lane >> 4) & 1) * 16;

    // ---- Q fragments resident in registers for the whole kt loop ----
    uint32_t aq[4][4];
    #pragma unroll
    for (int kc = 0; kc < 4; kc++)
        ldsm4(aq[kc], sb + SM_Q + SWZ(rowA * 128 + kc * 32 + cA16));

    float o[8][4];
    #pragma unroll
    for (int i = 0; i < 8; i++)
        #pragma unroll
        for (int e = 0; e < 4; e++) o[i][e] = 0.0f;
    float l0 = 0.0f, l1 = 0.0f;

    const int qmin = q0 + (warp << 4);
    const int qmax = qmin + 15;
    const int qr0  = qmin + g_;     // row of c0/c1
    const int lo0  = qr0 - (WINDOW - 1);
    const int lo1  = lo0 + 8;       // row qr0+8

    for (int kt = kt0; kt <= kt1; kt++) {
        asm volatile("cp.async.wait_group 0;" ::: "memory");
        __syncthreads();

        // overlap: issue async load of tile kt+1 into the other stage
        if (kt < kt1) {
            const char* ks = gk + (size_t)((kt + 1) * TK + srow) * 128 + sc0;
            const char* vs = gv + (size_t)((kt + 1) * TK + srow) * 128 + sc0;
            const uint32_t d = sb + SM_STG((kt + 1 - kt0) & 1);
            cpasync16(d + OFF_K + SWZ(srow * 128 + sc0),      ks);
            cpasync16(d + OFF_K + SWZ(srow * 128 + sc0 + 16), ks + 16);
            cpasync16(d + OFF_V + SWZ(srow * 128 + sc0),      vs);
            cpasync16(d + OFF_V + SWZ(srow * 128 + sc0 + 16), vs + 16);
            asm volatile("cp.async.commit_group;" ::: "memory");
        }

        // per-warp window skip (uniform across warp)
        const int jb = kt * TK;
        if (jb > qmax || jb + (TK - 1) < qmin - (WINDOW - 1)) continue;
        const bool fullv = (jb + (TK - 1) <= qmin) && (jb >= qmax - (WINDOW - 1));

        const uint32_t sk = sb + SM_STG((kt - kt0) & 1) + OFF_K;
        const uint32_t sv = sb + SM_STG((kt - kt0) & 1) + OFF_V;

        // ================= QK half 0 (keys jb..jb+31) =================
        float s[4][4];
        #pragma unroll
        for (int i = 0; i < 4; i++)
            #pragma unroll
            for (int e = 0; e < 4; e++) s[i][e] = 0.0f;

        #pragma unroll
        for (int kc = 0; kc < 4; kc++) {
            uint32_t kb0[4], kb1[4];
            ldsm4(kb0, sk + SWZ((0 * 16 + rkK) * 128 + kc * 32 + cK16));
            ldsm4(kb1, sk + SWZ((1 * 16 + rkK) * 128 + kc * 32 + cK16));
            mma16816(s[0], aq[kc], kb0[0], kb0[1]);
            mma16816(s[1], aq[kc], kb0[2], kb0[3]);
            mma16816(s[2], aq[kc], kb1[0], kb1[1]);
            mma16816(s[3], aq[kc], kb1[2], kb1[3]);
        }

        // ---- softmax half 0 -> pa0 ----
        uint32_t pa0[2][4];
        #pragma unroll
        for (int ln = 0; ln < 4; ln++) {
            float p0, p1, p2, p3;
            if (fullv) {
                p0 = ex2f_(s[ln][0]);
                p1 = ex2f_(s[ln][1]);
                p2 = ex2f_(s[ln][2]);
                p3 = ex2f_(s[ln][3]);
            } else {
                const int j0 = jb + ln * 8 + 2 * tig;
                const int j1 = j0 + 1;
                p0 = ((unsigned)(j0 - lo0) <= (WINDOW - 1)) ? ex2f_(s[ln][0]) : 0.0f;
                p1 = ((unsigned)(j1 - lo0) <= (WINDOW - 1)) ? ex2f_(s[ln][1]) : 0.0f;
                p2 = ((unsigned)(j0 - lo1) <= (WINDOW - 1)) ? ex2f_(s[ln][2]) : 0.0f;
                p3 = ((unsigned)(j1 - lo1) <= (WINDOW - 1)) ? ex2f_(s[ln][3]) : 0.0f;
            }
            l0 += p0 + p1;
            l1 += p2 + p3;
            const int c = ln >> 1, sub = ln & 1;
            pa0[c][sub * 2]     = pack2h(p0, p1);
            pa0[c][sub * 2 + 1] = pack2h(p2, p3);
        }

        // ===== interleaved: QK half 1 + PV half 0 (two independent chains) =====
        float s1[4][4];
        #pragma unroll
        for (int i = 0; i < 4; i++)
            #pragma unroll
            for (int e = 0; e < 4; e++) s1[i][e] = 0.0f;

        #pragma unroll
        for (int i = 0; i < 4; i++) {
            uint32_t kb0[4], kb1[4];
            ldsm4(kb0, sk + SWZ((2 * 16 + rkK) * 128 + i * 32 + cK16));
            ldsm4(kb1, sk + SWZ((3 * 16 + rkK) * 128 + i * 32 + cK16));
            // PV h0 slice: (c = i>>1, pr pair = (i&1)*2)
            const int c   = i >> 1;
            const int prb = (i & 1) * 2;
            uint32_t vb0[4], vb1[4];
            ldsm4t(vb0, sv + SWZ((c * 16 + rkV) * 128 + prb * 32 + cV16));
            ldsm4t(vb1, sv + SWZ((c * 16 + rkV) * 128 + (prb + 1) * 32 + cV16));
            mma16816(s1[0], aq[i], kb0[0], kb0[1]);
            mma16816(o[2 * prb],     pa0[c], vb0[0], vb0[1]);
            mma16816(s1[1], aq[i], kb0[2], kb0[3]);
            mma16816(o[2 * prb + 1], pa0[c], vb0[2], vb0[3]);
            mma16816(s1[2], aq[i], kb1[0], kb1[1]);
            mma16816(o[2 * prb + 2], pa0[c], vb1[0], vb1[1]);
            mma16816(s1[3], aq[i], kb1[2], kb1[3]);
            mma16816(o[2 * prb + 3], pa0[c], vb1[2], vb1[3]);
        }

        // ---- softmax half 1 -> pa1 ----
        uint32_t pa1[2][4];
        #pragma unroll
        for (int ln = 0; ln < 4; ln++) {
            float p0, p1, p2, p3;
            if (fullv) {
                p0 = ex2f_(s1[ln][0]);
                p1 = ex2f_(s1[ln][1]);
                p2 = ex2f_(s1[ln][2]);
                p3 = ex2f_(s1[ln][3]);
            } else {
                const int j0 = jb + 32 + ln * 8 + 2 * tig;
                const int j1 = j0 + 1;
                p0 = ((unsigned)(j0 - lo0) <= (WINDOW - 1)) ? ex2f_(s1[ln][0]) : 0.0f;
                p1 = ((unsigned)(j1 - lo0) <= (WINDOW - 1)) ? ex2f_(s1[ln][1]) : 0.0f;
                p2 = ((unsigned)(j0 - lo1) <= (WINDOW - 1)) ? ex2f_(s1[ln][2]) : 0.0f;
                p3 = ((unsigned)(j1 - lo1) <= (WINDOW - 1)) ? ex2f_(s1[ln][3]) : 0.0f;
            }
            l0 += p0 + p1;
            l1 += p2 + p3;
            const int c = ln >> 1, sub = ln & 1;
            pa1[c][sub * 2]     = pack2h(p0, p1);
            pa1[c][sub * 2 + 1] = pack2h(p2, p3);
        }

        // ---- PV half 1 ----
        #pragma unroll
        for (int c = 0; c < 2; c++) {
            const int kc2 = 2 + c;
            #pragma unroll
            for (int pr = 0; pr < 4; pr++) {
                uint32_t vb[4];
                ldsm4t(vb, sv + SWZ((kc2 * 16 + rkV) * 128 + pr * 32 + cV16));
                mma16816(o[2 * pr],     pa1[c], vb[0], vb[1]);
                mma16816(o[2 * pr + 1], pa1[c], vb[2], vb[3]);
            }
        }
    }

    // ---- finalize ----
    l0 += __shfl_xor_sync(0xffffffffu, l0, 1);
    l0 += __shfl_xor_sync(0xffffffffu, l0, 2);
    l1 += __shfl_xor_sync(0xffffffffu, l1, 1);
    l1 += __shfl_xor_sync(0xffffffffu, l1, 2);
    const float inv0 = 1.0f / l0;
    const float inv1 = 1.0f / l1;

    const int r0 = qr0;
    const int r1 = qr0 + 8;
    float* orow0 = Op + base + (size_t)r0 * DD;
    float* orow1 = Op + base + (size_t)r1 * DD;
    #pragma unroll
    for (int nb = 0; nb < 8; nb++) {
        const int c = nb * 8 + 2 * tig;
        *(float2*)(orow0 + c) = make_float2(o[nb][0] * inv0, o[nb][1] * inv0);
        *(float2*)(orow1 + c) = make_float2(o[nb][2] * inv1, o[nb][3] * inv1);
    }
}

extern "C" void kernel_launch(void* const* d_in, const int* in_sizes, int n_in,
                              void* d_out, int out_size) {
    const float* Q = (const float*)d_in[0];
    const float* K = (const float*)d_in[1];
    const float* V = (const float*)d_in[2];
    float* O = (float*)d_out;
    (void)in_sizes; (void)n_in; (void)out_size;

    cvt_kv_kernel<<<KV_CHUNKS / 512, 256>>>(K, V);

    cudaFuncSetAttribute(swa_mma_kernel, cudaFuncAttributeMaxDynamicSharedMemorySize, SM_TOTAL);
    dim3 grid(S_LEN / TQ, BH);   // (32, 16) = 512 blocks
    swa_mma_kernel<<<grid, NTH, SM_TOTAL>>>(Q, O);
}

// round 14
// speedup vs baseline: 1.4483x; 1.4483x over previous
#include <cuda_runtime.h>
#include <cuda_fp16.h>
#include <cstdint>

#define WINDOW 512
#define S_LEN  4096
#define BH     16
#define TQ     128
#define TK     64
#define DD     64
#define NTH    256

// smem: Q fp16 (16KB) + 2-stage K/V fp16 ring (2 x 16KB) = 48KB/CTA
#define SM_Q  0
#define SM_STG(s) (16384 + (s) * 16384)
#define OFF_K 0
#define OFF_V 8192
#define SM_TOTAL 49152

#define SWZ(x) ((x) ^ (((x) >> 3) & 0x70))

// fp16 K/V scratch: 16 * 4096 * 64 halves = 8MB each
#define KV_CHUNKS (BH * S_LEN * DD / 8)
__device__ uint4 g_kh[KV_CHUNKS];
__device__ uint4 g_vh[KV_CHUNKS];

static __device__ __forceinline__ uint32_t s2u(const void* p) {
    uint32_t a;
    asm("{ .reg .u64 t; cvta.to.shared.u64 t, %1; cvt.u32.u64 %0, t; }" : "=r"(a) : "l"(p));
    return a;
}
static __device__ __forceinline__ float ex2f_(float x) {
    float y; asm("ex2.approx.f32 %0,%1;" : "=f"(y) : "f"(x)); return y;
}
static __device__ __forceinline__ uint32_t pack2h(float a, float b) {
    uint32_t r;
    asm("cvt.rn.f16x2.f32 %0, %1, %2;" : "=r"(r) : "f"(b), "f"(a));
    return r;
}

static __device__ __forceinline__ void ldsm4(uint32_t r[4], uint32_t addr) {
    asm volatile("ldmatrix.sync.aligned.m8n8.x4.shared.b16 {%0,%1,%2,%3}, [%4];"
                 : "=r"(r[0]), "=r"(r[1]), "=r"(r[2]), "=r"(r[3]) : "r"(addr));
}
static __device__ __forceinline__ void ldsm4t(uint32_t r[4], uint32_t addr) {
    asm volatile("ldmatrix.sync.aligned.m8n8.x4.trans.shared.b16 {%0,%1,%2,%3}, [%4];"
                 : "=r"(r[0]), "=r"(r[1]), "=r"(r[2]), "=r"(r[3]) : "r"(addr));
}
static __device__ __forceinline__ void mma16816(float c[4], const uint32_t a[4],
                                                uint32_t b0, uint32_t b1) {
    asm volatile(
        "mma.sync.aligned.m16n8k16.row.col.f32.f16.f16.f32 "
        "{%0,%1,%2,%3}, {%4,%5,%6,%7}, {%8,%9}, {%0,%1,%2,%3};"
        : "+f"(c[0]), "+f"(c[1]), "+f"(c[2]), "+f"(c[3])
        : "r"(a[0]), "r"(a[1]), "r"(a[2]), "r"(a[3]), "r"(b0), "r"(b1));
}
static __device__ __forceinline__ void cpasync16(uint32_t sdst, const void* gsrc) {
    asm volatile("cp.async.cg.shared.global [%0], [%1], 16;"
                 :: "r"(sdst), "l"(gsrc) : "memory");
}

// 16 floats -> scaled fp16 tile (two 16B stores)
static __device__ __forceinline__ void store16h(const float4* g, char* s, int rel, float scale) {
    float4 f[4];
    #pragma unroll
    for (int i = 0; i < 4; i++) f[i] = g[i];
    uint32_t w[8];
    #pragma unroll
    for (int i = 0; i < 4; i++) {
        w[2 * i]     = pack2h(f[i].x * scale, f[i].y * scale);
        w[2 * i + 1] = pack2h(f[i].z * scale, f[i].w * scale);
    }
    *(uint4*)(s + SWZ(rel))      = make_uint4(w[0], w[1], w[2], w[3]);
    *(uint4*)(s + SWZ(rel + 16)) = make_uint4(w[4], w[5], w[6], w[7]);
}

// ---- prepass: K,V fp32 -> fp16 scratch; 2 chunks per tensor per thread (MLP 8) ----
__global__ void __launch_bounds__(256)
cvt_kv_kernel(const float* __restrict__ Kp, const float* __restrict__ Vp) {
    const int i = (blockIdx.x * 256 + threadIdx.x) * 2;   // exact: grid*256*2 == KV_CHUNKS
    const float4* ks = (const float4*)(Kp + (size_t)i * 8);
    const float4* vs = (const float4*)(Vp + (size_t)i * 8);
    float4 a = ks[0], b = ks[1], c = ks[2], d = ks[3];
    float4 e = vs[0], f = vs[1], g = vs[2], h = vs[3];
    g_kh[i]     = make_uint4(pack2h(a.x, a.y), pack2h(a.z, a.w),
                             pack2h(b.x, b.y), pack2h(b.z, b.w));
    g_kh[i + 1] = make_uint4(pack2h(c.x, c.y), pack2h(c.z, c.w),
                             pack2h(d.x, d.y), pack2h(d.z, d.w));
    g_vh[i]     = make_uint4(pack2h(e.x, e.y), pack2h(e.z, e.w),
                             pack2h(f.x, f.y), pack2h(f.z, f.w));
    g_vh[i + 1] = make_uint4(pack2h(g.x, g.y), pack2h(g.z, g.w),
                             pack2h(h.x, h.y), pack2h(h.z, h.w));
}

extern __shared__ __align__(1024) char smem[];

__global__ void __launch_bounds__(NTH, 2)
swa_mma_kernel(const float* __restrict__ Qp, float* __restrict__ Op) {
    const int tid  = threadIdx.x;
    const int lane = tid & 31;
    const int warp = tid >> 5;
    const int bh   = blockIdx.y;
    const int q0   = blockIdx.x * TQ;
    const size_t base = (size_t)bh * S_LEN * DD;
    const uint32_t sb = s2u(smem);

    // staging coords for cp.async
    const int srow = tid >> 2;
    const int sc0  = (tid & 3) * 32;
    const char* gk = (const char*)g_kh + (size_t)bh * S_LEN * 128;
    const char* gv = (const char*)g_vh + (size_t)bh * S_LEN * 128;

    const int kt0 = (q0 >= WINDOW - 1) ? ((q0 - WINDOW + 1) >> 6) : 0;
    const int kt1 = (q0 + TQ - 1) >> 6;

    // ---- prologue: async-load tile kt0 into stage 0 ----
    {
        const char* ks = gk + (size_t)(kt0 * TK + srow) * 128 + sc0;
        const char* vs = gv + (size_t)(kt0 * TK + srow) * 128 + sc0;
        const uint32_t d = sb + SM_STG(0);
        cpasync16(d + OFF_K + SWZ(srow * 128 + sc0),      ks);
        cpasync16(d + OFF_K + SWZ(srow * 128 + sc0 + 16), ks + 16);
        cpasync16(d + OFF_V + SWZ(srow * 128 + sc0),      vs);
        cpasync16(d + OFF_V + SWZ(srow * 128 + sc0 + 16), vs + 16);
        asm volatile("cp.async.commit_group;" ::: "memory");
    }

    // ---- stage Q (128x64) as fp16, pre-scaled to log2 domain ----
    {
        const float qs = 0.125f * 1.44269504088896340736f;
        const int trow = tid >> 2, q4 = tid & 3;
        #pragma unroll
        for (int half = 0; half < 2; half++) {
            const int row = trow + half * 64;
            const float4* g = (const float4*)(Qp + base + (size_t)(q0 + row) * DD + q4 * 16);
            store16h(g, smem + SM_Q, row * 128 + q4 * 32, qs);
        }
    }
    __syncthreads();

    // per-lane fragment address components
    const int g_   = lane >> 2;
    const int tig  = lane & 3;
    const int rowA = (warp << 4) + (lane & 15);
    const int cA16 = (lane >> 4) * 16;
    const int rkK  = (lane & 7) + ((lane >> 4) & 1) * 8;
    const int cK16 = ((lane >> 3) & 1) * 16;
    const int rkV  = (lane & 7) + ((lane >> 3) & 1) * 8;
    const int cV16 = ((lane >> 4) & 1) * 16;

    // ---- Q fragments resident in registers for the whole kt loop ----
    uint32_t aq[4][4];
    #pragma unroll
    for (int kc = 0; kc < 4; kc++)
        ldsm4(aq[kc], sb + SM_Q + SWZ(rowA * 128 + kc * 32 + cA16));

    float o[8][4];
    #pragma unroll
    for (int i = 0; i < 8; i++)
        #pragma unroll
        for (int e = 0; e < 4; e++) o[i][e] = 0.0f;
    float l0 = 0.0f, l1 = 0.0f;

    const int qmin = q0 + (warp << 4);
    const int qmax = qmin + 15;
    const int qr0  = qmin + g_;     // row of c0/c1
    const int lo0  = qr0 - (WINDOW - 1);
    const int lo1  = lo0 + 8;       // row qr0+8

    for (int kt = kt0; kt <= kt1; kt++) {
        asm volatile("cp.async.wait_group 0;" ::: "memory");
        __syncthreads();

        // overlap: issue async load of tile kt+1 into the other stage
        if (kt < kt1) {
            const char* ks = gk + (size_t)((kt + 1) * TK + srow) * 128 + sc0;
            const char* vs = gv + (size_t)((kt + 1) * TK + srow) * 128 + sc0;
            const uint32_t d = sb + SM_STG((kt + 1 - kt0) & 1);
            cpasync16(d + OFF_K + SWZ(srow * 128 + sc0),      ks);
            cpasync16(d + OFF_K + SWZ(srow * 128 + sc0 + 16), ks + 16);
            cpasync16(d + OFF_V + SWZ(srow * 128 + sc0),      vs);
            cpasync16(d + OFF_V + SWZ(srow * 128 + sc0 + 16), vs + 16);
            asm volatile("cp.async.commit_group;" ::: "memory");
        }

        // per-warp window skip (uniform across warp)
        const int jb = kt * TK;
        if (jb > qmax || jb + (TK - 1) < qmin - (WINDOW - 1)) continue;
        const bool fullv = (jb + (TK - 1) <= qmin) && (jb >= qmax - (WINDOW - 1));

        const uint32_t sk = sb + SM_STG((kt - kt0) & 1) + OFF_K;
        const uint32_t sv = sb + SM_STG((kt - kt0) & 1) + OFF_V;

        // ---- two n32-halves; each: QK -> softmax -> PV (P stays in registers) ----
        #pragma unroll
        for (int h = 0; h < 2; h++) {
            float s[4][4];
            #pragma unroll
            for (int i = 0; i < 4; i++)
                #pragma unroll
                for (int e = 0; e < 4; e++) s[i][e] = 0.0f;

            #pragma unroll
            for (int kc = 0; kc < 4; kc++) {
                uint32_t kb0[4], kb1[4];
                ldsm4(kb0, sk + SWZ(((2 * h)     * 16 + rkK) * 128 + kc * 32 + cK16));
                ldsm4(kb1, sk + SWZ(((2 * h + 1) * 16 + rkK) * 128 + kc * 32 + cK16));
                mma16816(s[0], aq[kc], kb0[0], kb0[1]);
                mma16816(s[1], aq[kc], kb0[2], kb0[3]);
                mma16816(s[2], aq[kc], kb1[0], kb1[1]);
                mma16816(s[3], aq[kc], kb1[2], kb1[3]);
            }

            // ---- softmax numerator + pack into PV A-fragments (single fp16) ----
            uint32_t pa[2][4];
            #pragma unroll
            for (int ln = 0; ln < 4; ln++) {
                const int nb = 4 * h + ln;
                float p0, p1, p2, p3;
                if (fullv) {
                    p0 = ex2f_(s[ln][0]);
                    p1 = ex2f_(s[ln][1]);
                    p2 = ex2f_(s[ln][2]);
                    p3 = ex2f_(s[ln][3]);
                } else {
                    const int j0 = jb + nb * 8 + 2 * tig;
                    const int j1 = j0 + 1;
                    p0 = ((unsigned)(j0 - lo0) <= (WINDOW - 1)) ? ex2f_(s[ln][0]) : 0.0f;
                    p1 = ((unsigned)(j1 - lo0) <= (WINDOW - 1)) ? ex2f_(s[ln][1]) : 0.0f;
                    p2 = ((unsigned)(j0 - lo1) <= (WINDOW - 1)) ? ex2f_(s[ln][2]) : 0.0f;
                    p3 = ((unsigned)(j1 - lo1) <= (WINDOW - 1)) ? ex2f_(s[ln][3]) : 0.0f;
                }
                l0 += p0 + p1;
                l1 += p2 + p3;
                const int c = ln >> 1, sub = ln & 1;
                pa[c][sub * 2]     = pack2h(p0, p1);
                pa[c][sub * 2 + 1] = pack2h(p2, p3);
            }

            // ---- PV for this half's two key chunks ----
            #pragma unroll
            for (int c = 0; c < 2; c++) {
                const int kc2 = 2 * h + c;
                #pragma unroll
                for (int pr = 0; pr < 4; pr++) {
                    uint32_t vb[4];
                    ldsm4t(vb, sv + SWZ((kc2 * 16 + rkV) * 128 + pr * 32 + cV16));
                    mma16816(o[2 * pr],     pa[c], vb[0], vb[1]);
                    mma16816(o[2 * pr + 1], pa[c], vb[2], vb[3]);
                }
            }
        }
    }

    // ---- finalize ----
    l0 += __shfl_xor_sync(0xffffffffu, l0, 1);
    l0 += __shfl_xor_sync(0xffffffffu, l0, 2);
    l1 += __shfl_xor_sync(0xffffffffu, l1, 1);
    l1 += __shfl_xor_sync(0xffffffffu, l1, 2);
    const float inv0 = 1.0f / l0;
    const float inv1 = 1.0f / l1;

    const int r0 = qr0;
    const int r1 = qr0 + 8;
    float* orow0 = Op + base + (size_t)r0 * DD;
    float* orow1 = Op + base + (size_t)r1 * DD;
    #pragma unroll
    for (int nb = 0; nb < 8; nb++) {
        const int c = nb * 8 + 2 * tig;
        *(float2*)(orow0 + c) = make_float2(o[nb][0] * inv0, o[nb][1] * inv0);
        *(float2*)(orow1 + c) = make_float2(o[nb][2] * inv1, o[nb][3] * inv1);
    }
}

extern "C" void kernel_launch(void* const* d_in, const int* in_sizes, int n_in,
                              void* d_out, int out_size) {
    const float* Q = (const float*)d_in[0];
    const float* K = (const float*)d_in[1];
    const float* V = (const float*)d_in[2];
    float* O = (float*)d_out;
    (void)in_sizes; (void)n_in; (void)out_size;

    cvt_kv_kernel<<<KV_CHUNKS / 512, 256>>>(K, V);

    cudaFuncSetAttribute(swa_mma_kernel, cudaFuncAttributeMaxDynamicSharedMemorySize, SM_TOTAL);
    dim3 grid(S_LEN / TQ, BH);   // (32, 16) = 512 blocks
    swa_mma_kernel<<<grid, NTH, SM_TOTAL>>>(Q, O);
}

// round 15
// speedup vs baseline: 1.5594x; 1.0767x over previous
#include <cuda_runtime.h>
#include <cuda_fp16.h>
#include <cstdint>

#define WINDOW 512
#define S_LEN  4096
#define BH     16
#define TQ     128
#define TK     64
#define DD     64
#define NTH    256

// smem: Q fp16 (16KB) + 2-stage K/V fp16 ring (2 x 16KB) = 48KB/CTA
#define SM_Q  0
#define SM_STG(s) (16384 + (s) * 16384)
#define OFF_K 0
#define OFF_V 8192
#define SM_TOTAL 49152

#define SWZ(x) ((x) ^ (((x) >> 3) & 0x70))

// fp16 K/V scratch: 16 * 4096 * 64 halves = 8MB each
#define KV_CHUNKS (BH * S_LEN * DD / 8)
__device__ uint4 g_kh[KV_CHUNKS];
__device__ uint4 g_vh[KV_CHUNKS];

static __device__ __forceinline__ uint32_t s2u(const void* p) {
    uint32_t a;
    asm("{ .reg .u64 t; cvta.to.shared.u64 t, %1; cvt.u32.u64 %0, t; }" : "=r"(a) : "l"(p));
    return a;
}
static __device__ __forceinline__ float ex2f_(float x) {
    float y; asm("ex2.approx.f32 %0,%1;" : "=f"(y) : "f"(x)); return y;
}
static __device__ __forceinline__ uint32_t pack2h(float a, float b) {
    uint32_t r;
    asm("cvt.rn.f16x2.f32 %0, %1, %2;" : "=r"(r) : "f"(b), "f"(a));
    return r;
}

static __device__ __forceinline__ void ldsm4(uint32_t r[4], uint32_t addr) {
    asm volatile("ldmatrix.sync.aligned.m8n8.x4.shared.b16 {%0,%1,%2,%3}, [%4];"
                 : "=r"(r[0]), "=r"(r[1]), "=r"(r[2]), "=r"(r[3]) : "r"(addr));
}
static __device__ __forceinline__ void ldsm4t(uint32_t r[4], uint32_t addr) {
    asm volatile("ldmatrix.sync.aligned.m8n8.x4.trans.shared.b16 {%0,%1,%2,%3}, [%4];"
                 : "=r"(r[0]), "=r"(r[1]), "=r"(r[2]), "=r"(r[3]) : "r"(addr));
}
static __device__ __forceinline__ void mma16816(float c[4], const uint32_t a[4],
                                                uint32_t b0, uint32_t b1) {
    asm volatile(
        "mma.sync.aligned.m16n8k16.row.col.f32.f16.f16.f32 "
        "{%0,%1,%2,%3}, {%4,%5,%6,%7}, {%8,%9}, {%0,%1,%2,%3};"
        : "+f"(c[0]), "+f"(c[1]), "+f"(c[2]), "+f"(c[3])
        : "r"(a[0]), "r"(a[1]), "r"(a[2]), "r"(a[3]), "r"(b0), "r"(b1));
}
static __device__ __forceinline__ void cpasync16(uint32_t sdst, const void* gsrc) {
    asm volatile("cp.async.cg.shared.global [%0], [%1], 16;"
                 :: "r"(sdst), "l"(gsrc) : "memory");
}

// 16 floats -> scaled fp16 tile (two 16B stores)
static __device__ __forceinline__ void store16h(const float4* g, char* s, int rel, float scale) {
    float4 f[4];
    #pragma unroll
    for (int i = 0; i < 4; i++) f[i] = g[i];
    uint32_t w[8];
    #pragma unroll
    for (int i = 0; i < 4; i++) {
        w[2 * i]     = pack2h(f[i].x * scale, f[i].y * scale);
        w[2 * i + 1] = pack2h(f[i].z * scale, f[i].w * scale);
    }
    *(uint4*)(s + SWZ(rel))      = make_uint4(w[0], w[1], w[2], w[3]);
    *(uint4*)(s + SWZ(rel + 16)) = make_uint4(w[4], w[5], w[6], w[7]);
}

// ---- prepass: K,V fp32 -> fp16 scratch; 2 chunks per tensor per thread (MLP 8) ----
__global__ void __launch_bounds__(256)
cvt_kv_kernel(const float* __restrict__ Kp, const float* __restrict__ Vp) {
    const int i = (blockIdx.x * 256 + threadIdx.x) * 2;   // exact: grid*256*2 == KV_CHUNKS
    const float4* ks = (const float4*)(Kp + (size_t)i * 8);
    const float4* vs = (const float4*)(Vp + (size_t)i * 8);
    float4 a = ks[0], b = ks[1], c = ks[2], d = ks[3];
    float4 e = vs[0], f = vs[1], g = vs[2], h = vs[3];
    g_kh[i]     = make_uint4(pack2h(a.x, a.y), pack2h(a.z, a.w),
                             pack2h(b.x, b.y), pack2h(b.z, b.w));
    g_kh[i + 1] = make_uint4(pack2h(c.x, c.y), pack2h(c.z, c.w),
                             pack2h(d.x, d.y), pack2h(d.z, d.w));
    g_vh[i]     = make_uint4(pack2h(e.x, e.y), pack2h(e.z, e.w),
                             pack2h(f.x, f.y), pack2h(f.z, f.w));
    g_vh[i + 1] = make_uint4(pack2h(g.x, g.y), pack2h(g.z, g.w),
                             pack2h(h.x, h.y), pack2h(h.z, h.w));
}

extern __shared__ __align__(1024) char smem[];

__global__ void __launch_bounds__(NTH, 2)
swa_mma_kernel(const float* __restrict__ Qp, float* __restrict__ Op) {
    const int tid  = threadIdx.x;
    const int lane = tid & 31;
    const int warp = tid >> 5;
    // LPT ordering: heaviest q-blocks (largest x => most key tiles) launch first.
    const int bid  = blockIdx.x;
    const int bh   = bid & (BH - 1);
    const int q0   = ((S_LEN / TQ - 1) - (bid >> 4)) * TQ;
    const size_t base = (size_t)bh * S_LEN * DD;
    const uint32_t sb = s2u(smem);

    // staging coords for cp.async
    const int srow = tid >> 2;
    const int sc0  = (tid & 3) * 32;
    const char* gk = (const char*)g_kh + (size_t)bh * S_LEN * 128;
    const char* gv = (const char*)g_vh + (size_t)bh * S_LEN * 128;

    const int kt0 = (q0 >= WINDOW - 1) ? ((q0 - WINDOW + 1) >> 6) : 0;
    const int kt1 = (q0 + TQ - 1) >> 6;

    // ---- prologue: async-load tile kt0 into stage 0 ----
    {
        const char* ks = gk + (size_t)(kt0 * TK + srow) * 128 + sc0;
        const char* vs = gv + (size_t)(kt0 * TK + srow) * 128 + sc0;
        const uint32_t d = sb + SM_STG(0);
        cpasync16(d + OFF_K + SWZ(srow * 128 + sc0),      ks);
        cpasync16(d + OFF_K + SWZ(srow * 128 + sc0 + 16), ks + 16);
        cpasync16(d + OFF_V + SWZ(srow * 128 + sc0),      vs);
        cpasync16(d + OFF_V + SWZ(srow * 128 + sc0 + 16), vs + 16);
        asm volatile("cp.async.commit_group;" ::: "memory");
    }

    // ---- stage Q (128x64) as fp16, pre-scaled to log2 domain ----
    {
        const float qs = 0.125f * 1.44269504088896340736f;
        const int trow = tid >> 2, q4 = tid & 3;
        #pragma unroll
        for (int half = 0; half < 2; half++) {
            const int row = trow + half * 64;
            const float4* g = (const float4*)(Qp + base + (size_t)(q0 + row) * DD + q4 * 16);
            store16h(g, smem + SM_Q, row * 128 + q4 * 32, qs);
        }
    }
    __syncthreads();

    // per-lane fragment address components
    const int g_   = lane >> 2;
    const int tig  = lane & 3;
    const int rowA = (warp << 4) + (lane & 15);
    const int cA16 = (lane >> 4) * 16;
    const int rkK  = (lane & 7) + ((lane >> 4) & 1) * 8;
    const int cK16 = ((lane >> 3) & 1) * 16;
    const int rkV  = (lane & 7) + ((lane >> 3) & 1) * 8;
    const int cV16 = ((lane >> 4) & 1) * 16;

    // ---- Q fragments resident in registers for the whole kt loop ----
    uint32_t aq[4][4];
    #pragma unroll
    for (int kc = 0; kc < 4; kc++)
        ldsm4(aq[kc], sb + SM_Q + SWZ(rowA * 128 + kc * 32 + cA16));

    float o[8][4];
    #pragma unroll
    for (int i = 0; i < 8; i++)
        #pragma unroll
        for (int e = 0; e < 4; e++) o[i][e] = 0.0f;
    float l0 = 0.0f, l1 = 0.0f;

    const int qmin = q0 + (warp << 4);
    const int qmax = qmin + 15;
    const int qr0  = qmin + g_;     // row of c0/c1
    const int lo0  = qr0 - (WINDOW - 1);
    const int lo1  = lo0 + 8;       // row qr0+8

    for (int kt = kt0; kt <= kt1; kt++) {
        asm volatile("cp.async.wait_group 0;" ::: "memory");
        __syncthreads();

        // overlap: issue async load of tile kt+1 into the other stage
        if (kt < kt1) {
            const char* ks = gk + (size_t)((kt + 1) * TK + srow) * 128 + sc0;
            const char* vs = gv + (size_t)((kt + 1) * TK + srow) * 128 + sc0;
            const uint32_t d = sb + SM_STG((kt + 1 - kt0) & 1);
            cpasync16(d + OFF_K + SWZ(srow * 128 + sc0),      ks);
            cpasync16(d + OFF_K + SWZ(srow * 128 + sc0 + 16), ks + 16);
            cpasync16(d + OFF_V + SWZ(srow * 128 + sc0),      vs);
            cpasync16(d + OFF_V + SWZ(srow * 128 + sc0 + 16), vs + 16);
            asm volatile("cp.async.commit_group;" ::: "memory");
        }

        // per-warp window skip (uniform across warp)
        const int jb = kt * TK;
        if (jb > qmax || jb + (TK - 1) < qmin - (WINDOW - 1)) continue;
        const bool fullv = (jb + (TK - 1) <= qmin) && (jb >= qmax - (WINDOW - 1));

        const uint32_t sk = sb + SM_STG((kt - kt0) & 1) + OFF_K;
        const uint32_t sv = sb + SM_STG((kt - kt0) & 1) + OFF_V;

        // ---- two n32-halves; each: QK -> softmax -> PV (P stays in registers) ----
        #pragma unroll
        for (int h = 0; h < 2; h++) {
            float s[4][4];
            #pragma unroll
            for (int i = 0; i < 4; i++)
                #pragma unroll
                for (int e = 0; e < 4; e++) s[i][e] = 0.0f;

            #pragma unroll
            for (int kc = 0; kc < 4; kc++) {
                uint32_t kb0[4], kb1[4];
                ldsm4(kb0, sk + SWZ(((2 * h)     * 16 + rkK) * 128 + kc * 32 + cK16));
                ldsm4(kb1, sk + SWZ(((2 * h + 1) * 16 + rkK) * 128 + kc * 32 + cK16));
                mma16816(s[0], aq[kc], kb0[0], kb0[1]);
                mma16816(s[1], aq[kc], kb0[2], kb0[3]);
                mma16816(s[2], aq[kc], kb1[0], kb1[1]);
                mma16816(s[3], aq[kc], kb1[2], kb1[3]);
            }

            // ---- softmax numerator + pack into PV A-fragments (single fp16) ----
            uint32_t pa[2][4];
            #pragma unroll
            for (int ln = 0; ln < 4; ln++) {
                const int nb = 4 * h + ln;
                float p0, p1, p2, p3;
                if (fullv) {
                    p0 = ex2f_(s[ln][0]);
                    p1 = ex2f_(s[ln][1]);
                    p2 = ex2f_(s[ln][2]);
                    p3 = ex2f_(s[ln][3]);
                } else {
                    const int j0 = jb + nb * 8 + 2 * tig;
                    const int j1 = j0 + 1;
                    p0 = ((unsigned)(j0 - lo0) <= (WINDOW - 1)) ? ex2f_(s[ln][0]) : 0.0f;
                    p1 = ((unsigned)(j1 - lo0) <= (WINDOW - 1)) ? ex2f_(s[ln][1]) : 0.0f;
                    p2 = ((unsigned)(j0 - lo1) <= (WINDOW - 1)) ? ex2f_(s[ln][2]) : 0.0f;
                    p3 = ((unsigned)(j1 - lo1) <= (WINDOW - 1)) ? ex2f_(s[ln][3]) : 0.0f;
                }
                l0 += p0 + p1;
                l1 += p2 + p3;
                const int c = ln >> 1, sub = ln & 1;
                pa[c][sub * 2]     = pack2h(p0, p1);
                pa[c][sub * 2 + 1] = pack2h(p2, p3);
            }

            // ---- PV for this half's two key chunks ----
            #pragma unroll
            for (int c = 0; c < 2; c++) {
                const int kc2 = 2 * h + c;
                #pragma unroll
                for (int pr = 0; pr < 4; pr++) {
                    uint32_t vb[4];
                    ldsm4t(vb, sv + SWZ((kc2 * 16 + rkV) * 128 + pr * 32 + cV16));
                    mma16816(o[2 * pr],     pa[c], vb[0], vb[1]);
                    mma16816(o[2 * pr + 1], pa[c], vb[2], vb[3]);
                }
            }
        }
    }

    // ---- finalize ----
    l0 += __shfl_xor_sync(0xffffffffu, l0, 1);
    l0 += __shfl_xor_sync(0xffffffffu, l0, 2);
    l1 += __shfl_xor_sync(0xffffffffu, l1, 1);
    l1 += __shfl_xor_sync(0xffffffffu, l1, 2);
    const float inv0 = 1.0f / l0;
    const float inv1 = 1.0f / l1;

    const int r0 = qr0;
    const int r1 = qr0 + 8;
    float* orow0 = Op + base + (size_t)r0 * DD;
    float* orow1 = Op + base + (size_t)r1 * DD;
    #pragma unroll
    for (int nb = 0; nb < 8; nb++) {
        const int c = nb * 8 + 2 * tig;
        *(float2*)(orow0 + c) = make_float2(o[nb][0] * inv0, o[nb][1] * inv0);
        *(float2*)(orow1 + c) = make_float2(o[nb][2] * inv1, o[nb][3] * inv1);
    }
}

extern "C" void kernel_launch(void* const* d_in, const int* in_sizes, int n_in,
                              void* d_out, int out_size) {
    const float* Q = (const float*)d_in[0];
    const float* K = (const float*)d_in[1];
    const float* V = (const float*)d_in[2];
    float* O = (float*)d_out;
    (void)in_sizes; (void)n_in; (void)out_size;

    cvt_kv_kernel<<<KV_CHUNKS / 512, 256>>>(K, V);

    cudaFuncSetAttribute(swa_mma_kernel, cudaFuncAttributeMaxDynamicSharedMemorySize, SM_TOTAL);
    swa_mma_kernel<<<(S_LEN / TQ) * BH, NTH, SM_TOTAL>>>(Q, O);   // 512 blocks, LPT-ordered
}